// round 13
// baseline (speedup 1.0000x reference)
#include <cuda_runtime.h>
#include <cuda_bf16.h>
#include <cuda_fp16.h>
#include <cstdint>

#define NSEQ    512
#define EMB     128
#define HDIM    16
#define NBATCH  512          // B*H*C
#define M_TOTAL 32768        // B*C*N

// Scratch (__device__ globals per allocation rules)
// Q,K packed bf16 hi/lo, FRAG-PAIRED word order within each 8-word group:
//   pos = (j&3)*2 + (j>>2)  (j = natural word index 0..7; word j = k elems 2j,2j+1)
// row layout: [g][n][w0..7 = hi paired, w8..15 = lo paired]; Q pre-scaled by 1/4
__device__ uint32_t g_qp[NBATCH * NSEQ * 16];
__device__ uint32_t g_kp[NBATCH * NSEQ * 16];
// V fp16 transposed [g][d][n], n-words frag-paired within each 8-word group
__device__ __half   g_vp[NBATCH * HDIM * NSEQ];
__device__ float    g_att[(size_t)M_TOTAL * EMB];
// Preconverted weights, frag-interleaved: [which][(n*8+ks)*4+tig] = {bh0,bh1,bl0,bl1}
__device__ uint4    g_wf[4][4096];

// ---------------------------------------------------------------------------
// mma.sync m16n8k16 (arch-unconditional HMMA)
// A frags (lane=4*gid+tig): a0=(gid,2tig) a1=(gid+8,2tig) a2=(gid,2tig+8) a3=(gid+8,2tig+8)
// B frags: b0=(k=2tig,n=gid) b1=(k=2tig+8,n=gid)
// C frags: c0=(gid,2tig) c1=(gid,2tig+1) c2=(gid+8,2tig) c3=(gid+8,2tig+1)
// ---------------------------------------------------------------------------
__device__ __forceinline__ void mma16816(float* c, const uint32_t* a, const uint32_t* b) {
    asm volatile(
        "mma.sync.aligned.m16n8k16.row.col.f32.bf16.bf16.f32 "
        "{%0,%1,%2,%3}, {%4,%5,%6,%7}, {%8,%9}, {%0,%1,%2,%3};"
        : "+f"(c[0]), "+f"(c[1]), "+f"(c[2]), "+f"(c[3])
        : "r"(a[0]), "r"(a[1]), "r"(a[2]), "r"(a[3]), "r"(b[0]), "r"(b[1]));
}
__device__ __forceinline__ void mma16816h(float* c, const uint32_t* a, const uint32_t* b) {
    asm volatile(
        "mma.sync.aligned.m16n8k16.row.col.f32.f16.f16.f32 "
        "{%0,%1,%2,%3}, {%4,%5,%6,%7}, {%8,%9}, {%0,%1,%2,%3};"
        : "+f"(c[0]), "+f"(c[1]), "+f"(c[2]), "+f"(c[3])
        : "r"(a[0]), "r"(a[1]), "r"(a[2]), "r"(a[3]), "r"(b[0]), "r"(b[1]));
}

// Split two floats into packed bf16x2 hi + lo (low 16 bits = first element)
__device__ __forceinline__ void pack_split(float p0, float p1, uint32_t& h, uint32_t& l) {
    asm("cvt.rn.bf16x2.f32 %0, %1, %2;" : "=r"(h) : "f"(p1), "f"(p0));
    float h0 = __uint_as_float(h << 16);
    float h1 = __uint_as_float(h & 0xFFFF0000u);
    float l0 = p0 - h0, l1 = p1 - h1;
    asm("cvt.rn.bf16x2.f32 %0, %1, %2;" : "=r"(l) : "f"(l1), "f"(l0));
}

// ---------------------------------------------------------------------------
// One-shot weight conversion -> frag-interleaved hi/lo layout
// ---------------------------------------------------------------------------
__global__ __launch_bounds__(256) void wconv(const float* __restrict__ Wq,
                                             const float* __restrict__ Wk,
                                             const float* __restrict__ Wv,
                                             const float* __restrict__ Wout) {
    const int i     = blockIdx.x * 256 + threadIdx.x;   // 0..16383
    const int which = i >> 12;
    const int r     = i & 4095;
    const int n     = r >> 5;
    const int ks    = (r >> 2) & 7;
    const int tig   = r & 3;
    const int k0    = ks * 16 + 2 * tig;
    const float* W  = (which == 0) ? Wq : (which == 1) ? Wk : (which == 2) ? Wv : Wout;
    float2 a = *(const float2*)(W + n * EMB + k0);
    float2 b = *(const float2*)(W + n * EMB + k0 + 8);
    uint4 o;
    pack_split(a.x, a.y, o.x, o.z);
    pack_split(b.x, b.y, o.y, o.w);
    g_wf[which][r] = o;
}

// ---------------------------------------------------------------------------
// Split-bf16 GEMM tile: out[128 x 128] = X[128,128] @ W^T. X hi/lo in smem
// (frag-paired word order -> LDS.64 A-frags); W frags via LDG.128 with
// register double-buffer prefetch.
// mode 0: fp32 [m][f]; mode 1: packed bf16 hi/lo paired [g][n][16w] (scaled by sc);
// mode 2: fp16 [g][d][n] paired
// ---------------------------------------------------------------------------
#define XS 144                                 // elements per row (72 words; 72%32=8)
#define TILE_ELEMS (128 * XS)
#define GEMM_SMEM (2 * TILE_ELEMS * 2)         // 73728 B

__device__ __forceinline__ void gemm_tile_mma(const float* __restrict__ X,
                                              const uint4* __restrict__ wf,
                                              void* __restrict__ outv,
                                              int mode, float sc, int tile,
                                              __nv_bfloat16* sm) {
    __nv_bfloat16* sXh = sm;
    __nv_bfloat16* sXl = sm + TILE_ELEMS;
    const int tid  = threadIdx.x;
    const int row0 = tile * 128;

    // fill X hi/lo with frag-paired word order:
    // c4 group -> words (j, j+1), j = (c4>>1)&7 even; pos = (j&3)*2+(j>>2), pos+2
    {
        const float4* Xv = (const float4*)(X + (size_t)row0 * EMB);
        for (int i = tid; i < 4096; i += 256) {
            const int r  = i >> 5;
            const int c4 = (i & 31) << 2;
            const int ks = c4 >> 4;
            const int j  = (c4 >> 1) & 7;                  // 0,2,4,6
            const int pj = ((j & 3) << 1) | (j >> 2);      // 0,4,1,5
            const int base = r * XS + ks * 16 + 2 * pj;    // element offset
            float4 v = Xv[i];
            uint32_t h01, h23, l01, l23;
            pack_split(v.x, v.y, h01, l01);
            pack_split(v.z, v.w, h23, l23);
            uint32_t* dh = (uint32_t*)(sXh + base);
            uint32_t* dl = (uint32_t*)(sXl + base);
            dh[0] = h01; dh[2] = h23;
            dl[0] = l01; dl[2] = l23;
        }
    }
    __syncthreads();

    const int lane = tid & 31;
    const int wid  = tid >> 5;
    const int gid  = lane >> 2;
    const int tig  = lane & 3;
    const int wm   = (wid & 1) * 64;
    const int wn   = (wid >> 1) * 32;

    float acc[4][4][4];
#pragma unroll
    for (int mt = 0; mt < 4; mt++)
#pragma unroll
        for (int nt = 0; nt < 4; nt++)
#pragma unroll
            for (int j = 0; j < 4; j++) acc[mt][nt][j] = 0.f;

    // W-frag register double-buffer
    uint4 wcur[4];
#pragma unroll
    for (int nt = 0; nt < 4; nt++)
        wcur[nt] = wf[((wn + nt * 8 + gid) * 8 + 0) * 4 + tig];

#pragma unroll 1
    for (int ks = 0; ks < 8; ks++) {
        uint4 wnxt[4];
        const int ksn = (ks + 1) & 7;
#pragma unroll
        for (int nt = 0; nt < 4; nt++)
            wnxt[nt] = wf[((wn + nt * 8 + gid) * 8 + ksn) * 4 + tig];

        uint32_t bh[4][2], bl[4][2];
#pragma unroll
        for (int nt = 0; nt < 4; nt++) {
            bh[nt][0] = wcur[nt].x;
            bh[nt][1] = wcur[nt].y;
            bl[nt][0] = wcur[nt].z;
            bl[nt][1] = wcur[nt].w;
        }
#pragma unroll
        for (int mt = 0; mt < 4; mt++) {
            const int r = wm + mt * 16 + gid;
            const __nv_bfloat16* p = sXh + r * XS + ks * 16 + 4 * tig;
            const __nv_bfloat16* q = sXl + r * XS + ks * 16 + 4 * tig;
            uint32_t ah[4], al[4];
            {
                uint2 a0 = *(const uint2*)p;
                uint2 a1 = *(const uint2*)(p + 8 * XS);
                uint2 b0 = *(const uint2*)q;
                uint2 b1 = *(const uint2*)(q + 8 * XS);
                ah[0] = a0.x; ah[2] = a0.y;
                ah[1] = a1.x; ah[3] = a1.y;
                al[0] = b0.x; al[2] = b0.y;
                al[1] = b1.x; al[3] = b1.y;
            }
#pragma unroll
            for (int nt = 0; nt < 4; nt++) {
                mma16816(acc[mt][nt], ah, bh[nt]);
                mma16816(acc[mt][nt], al, bh[nt]);
                mma16816(acc[mt][nt], ah, bl[nt]);
            }
        }
#pragma unroll
        for (int nt = 0; nt < 4; nt++) wcur[nt] = wnxt[nt];
    }

#pragma unroll
    for (int mt = 0; mt < 4; mt++) {
#pragma unroll
        for (int nt = 0; nt < 4; nt++) {
            const int f = wn + nt * 8 + 2 * tig;
#pragma unroll
            for (int half = 0; half < 2; half++) {
                const int m = row0 + wm + mt * 16 + gid + half * 8;
                float2 v = make_float2(acc[mt][nt][half * 2], acc[mt][nt][half * 2 + 1]);
                const int b = m >> 10, c = (m >> 9) & 1, n = m & 511;
                const int h = f >> 4, dd = f & 15;
                const int g = b * 16 + h * 2 + c;
                if (mode == 1) {
                    uint32_t hh, ll;
                    pack_split(v.x * sc, v.y * sc, hh, ll);
                    const int j  = dd >> 1;
                    const int pj = ((j & 3) << 1) | (j >> 2);
                    uint32_t* row = (uint32_t*)outv + ((size_t)(g * NSEQ + n)) * 16;
                    row[pj]     = hh;
                    row[8 + pj] = ll;
                } else if (mode == 2) {
                    // permuted n-position within 8-word group
                    const int w  = n >> 1, jj = w & 7, grp = w & ~7;
                    const int pw = grp + (((jj & 3) << 1) | (jj >> 2));
                    const int ei = (pw << 1) | (n & 1);
                    __half* vp = (__half*)outv + (size_t)g * 8192;
                    vp[dd * 512 + ei]       = __float2half_rn(v.x);
                    vp[(dd + 1) * 512 + ei] = __float2half_rn(v.y);
                } else {
                    *(float2*)((float*)outv + (size_t)m * EMB + f) = v;
                }
            }
        }
    }
}

__global__ __launch_bounds__(256) void proj3_mma(const float* __restrict__ Q,
                                                 const float* __restrict__ K,
                                                 const float* __restrict__ V) {
    extern __shared__ __align__(16) __nv_bfloat16 smem[];
    const int which = blockIdx.x >> 8;
    const int tile  = blockIdx.x & 255;
    const float* X = (which == 0) ? Q : (which == 1) ? K : V;
    void* O        = (which == 0) ? (void*)g_qp : (which == 1) ? (void*)g_kp : (void*)g_vp;
    const float sc = (which == 0) ? 0.25f : 1.0f;   // fold s/4 into Q
    gemm_tile_mma(X, g_wf[which], O, (which == 2) ? 2 : 1, sc, tile, smem);
}

__global__ __launch_bounds__(256) void outproj_mma(const float* __restrict__ X,
                                                   float* __restrict__ out) {
    extern __shared__ __align__(16) __nv_bfloat16 smem[];
    gemm_tile_mma(X, g_wf[3], out, 0, 1.0f, blockIdx.x, smem);
}

// ---------------------------------------------------------------------------
// HMMA attention. grid = 1024: block = (g, qhalf); 8 warps x 32 q-rows.
// QK: split-bf16 3-mma (q pre-scaled by 1/4). Softmax: p = 2^(K*(tanh(s)-1)).
// PV: fp16 mma; denominator via ones-B-frag mma.
// Frag-paired layouts -> all fragment loads are LDS.64 (conflict-free).
// K: stride 8 words; V: stride 264 words.
// ---------------------------------------------------------------------------
#define VW 264
#define ATTN_WORDS (4096 + 4096 + 16 * VW + 256)
#define ATTN_SMEM  (ATTN_WORDS * 4)            // 50688 B

__global__ __launch_bounds__(256) void attn_mma(const float* __restrict__ mask) {
    extern __shared__ __align__(16) uint32_t smu[];
    uint32_t* khi = smu;                        // [key][8] paired
    uint32_t* klo = smu + 4096;                 // [key][8] paired
    uint32_t* vsm = smu + 8192;                 // [d][264] paired
    uint32_t* msm = smu + 8192 + 16 * VW;       // f16x2 mask pairs [256]

    const int g    = blockIdx.x >> 1;
    const int qhx  = blockIdx.x & 1;
    const int tid  = threadIdx.x;
    const int b = g >> 4, h = (g >> 1) & 7, c = g & 1;
    const int lane = tid & 31;
    const int wid  = tid >> 5;
    const int gid  = lane >> 2;
    const int tig  = lane & 3;

    // ---- copy precomputed K/V into smem (pure uint4 copies) ----
    {
        const uint4* kg = (const uint4*)(g_kp + (size_t)g * 8192);
        for (int i = tid; i < 2048; i += 256) {
            uint4 w = kg[i];
            const int key = i >> 2, seg = i & 3;
            uint32_t* dst = (seg < 2) ? (khi + key * 8 + 4 * seg)
                                      : (klo + key * 8 + 4 * (seg - 2));
            dst[0] = w.x; dst[1] = w.y; dst[2] = w.z; dst[3] = w.w;
        }
        const uint4* vg = (const uint4*)(g_vp + (size_t)g * 8192);
        for (int i = tid; i < 1024; i += 256) {
            uint4 w = vg[i];
            const int d = i >> 6, j4 = (i & 63) * 4;
            uint32_t* dst = vsm + d * VW + j4;
            dst[0] = w.x; dst[1] = w.y; dst[2] = w.z; dst[3] = w.w;
        }
        const unsigned* mrow = (const unsigned*)mask + (b * 2 + c) * NSEQ;
        for (int i = tid; i < 256; i += 256) {
            float m0 = (mrow[2 * i] != 0u) ? 0.f : 1.f;
            float m1 = (mrow[2 * i + 1] != 0u) ? 0.f : 1.f;
            __half2 mh = __floats2half2_rn(m0, m1);
            msm[i] = *(uint32_t*)&mh;
        }
    }

    // ---- Q fragments: paired 8-byte loads from global ----
    uint32_t qh[2][4], ql[2][4];
    {
        const uint32_t* qg = g_qp + (size_t)g * 8192 + (size_t)(qhx * 256 + wid * 32) * 16;
#pragma unroll
        for (int mt = 0; mt < 2; mt++) {
            const uint32_t* r0 = qg + (mt * 16 + gid) * 16;
            const uint32_t* r1 = r0 + 128;
            uint2 a = *(const uint2*)(r0 + 2 * tig);
            uint2 bb = *(const uint2*)(r1 + 2 * tig);
            uint2 cc = *(const uint2*)(r0 + 8 + 2 * tig);
            uint2 dd2 = *(const uint2*)(r1 + 8 + 2 * tig);
            qh[mt][0] = a.x;  qh[mt][2] = a.y;
            qh[mt][1] = bb.x; qh[mt][3] = bb.y;
            ql[mt][0] = cc.x; ql[mt][2] = cc.y;
            ql[mt][1] = dd2.x; ql[mt][3] = dd2.y;
        }
    }
    __syncthreads();

    float oacc[2][2][4];
    float dacc[2][4];
#pragma unroll
    for (int mt = 0; mt < 2; mt++) {
#pragma unroll
        for (int j = 0; j < 4; j++) dacc[mt][j] = 0.f;
#pragma unroll
        for (int dnt = 0; dnt < 2; dnt++)
#pragma unroll
            for (int j = 0; j < 4; j++) oacc[mt][dnt][j] = 0.f;
    }

    const float KTH = 14.4269504089f;   // 10*log2(e)
    uint32_t bones[2];
    bones[0] = bones[1] = (gid == 0) ? 0x3C003C00u : 0u;      // ones col 0

#pragma unroll 1
    for (int ch = 0; ch < 16; ch++) {
        float s[2][4][4];
#pragma unroll
        for (int mt = 0; mt < 2; mt++)
#pragma unroll
            for (int nt = 0; nt < 4; nt++)
#pragma unroll
                for (int j = 0; j < 4; j++) s[mt][nt][j] = 0.f;

#pragma unroll
        for (int nt = 0; nt < 4; nt++) {
            const int key = ch * 32 + nt * 8 + gid;
            uint2 kh2 = *(const uint2*)(khi + key * 8 + 2 * tig);
            uint2 kl2 = *(const uint2*)(klo + key * 8 + 2 * tig);
            uint32_t kh[2] = {kh2.x, kh2.y};
            uint32_t kl[2] = {kl2.x, kl2.y};
#pragma unroll
            for (int mt = 0; mt < 2; mt++) {
                mma16816(s[mt][nt], qh[mt], kh);
                mma16816(s[mt][nt], ql[mt], kh);
                mma16816(s[mt][nt], qh[mt], kl);
            }
        }

        // softmax: p = 2^(KTH*(tanh(s)-1)) * mask
        uint32_t pf[2][4][2];
#pragma unroll
        for (int nt = 0; nt < 4; nt++) {
            const uint32_t mword = msm[ch * 16 + nt * 4 + tig];
            const __half2 m2h = *(const __half2*)&mword;
#pragma unroll
            for (int mt = 0; mt < 2; mt++) {
#pragma unroll
                for (int pi = 0; pi < 2; pi++) {
                    float t0, t1;
                    asm("tanh.approx.f32 %0, %1;" : "=f"(t0) : "f"(s[mt][nt][pi * 2]));
                    asm("tanh.approx.f32 %0, %1;" : "=f"(t1) : "f"(s[mt][nt][pi * 2 + 1]));
                    const float y0 = fmaf(KTH, t0, -KTH);
                    const float y1 = fmaf(KTH, t1, -KTH);
                    uint32_t yw, pw;
                    asm("cvt.rn.f16x2.f32 %0, %1, %2;" : "=r"(yw) : "f"(y1), "f"(y0));
                    asm("ex2.approx.f16x2 %0, %1;" : "=r"(pw) : "r"(yw));
                    __half2 p = *(__half2*)&pw;
                    p = __hmul2(p, m2h);
                    pf[mt][nt][pi] = *(uint32_t*)&p;
                }
            }
        }

        // PV + denominator accumulate (fp16 mma)
#pragma unroll
        for (int ks = 0; ks < 2; ks++) {
            uint32_t vh[2][2];
#pragma unroll
            for (int dnt = 0; dnt < 2; dnt++) {
                const int d = dnt * 8 + gid;
                uint2 v2 = *(const uint2*)(vsm + d * VW + ch * 16 + ks * 8 + 2 * tig);
                vh[dnt][0] = v2.x;
                vh[dnt][1] = v2.y;
            }
#pragma unroll
            for (int mt = 0; mt < 2; mt++) {
                uint32_t ap[4] = {pf[mt][2 * ks][0], pf[mt][2 * ks][1],
                                  pf[mt][2 * ks + 1][0], pf[mt][2 * ks + 1][1]};
                mma16816h(oacc[mt][0], ap, vh[0]);
                mma16816h(oacc[mt][1], ap, vh[1]);
                mma16816h(dacc[mt], ap, bones);
            }
        }
    }

    // denominators live in tig==0 lanes: dacc[mt][0] = row gid, [2] = row gid+8
    float inv[2][2];
#pragma unroll
    for (int mt = 0; mt < 2; mt++) {
        float i0 = 1.f / dacc[mt][0];
        float i1 = 1.f / dacc[mt][2];
        inv[mt][0] = __shfl_sync(0xFFFFFFFFu, i0, lane & ~3);
        inv[mt][1] = __shfl_sync(0xFFFFFFFFu, i1, lane & ~3);
    }

    const int mbase = (b * 2 + c) * NSEQ;
#pragma unroll
    for (int mt = 0; mt < 2; mt++) {
        const int row = qhx * 256 + wid * 32 + mt * 16 + gid;
#pragma unroll
        for (int dnt = 0; dnt < 2; dnt++) {
            const int dcol = h * HDIM + dnt * 8 + 2 * tig;
            float* o0 = g_att + (size_t)(mbase + row) * EMB + dcol;
            float* o1 = g_att + (size_t)(mbase + row + 8) * EMB + dcol;
            *(float2*)o0 = make_float2(oacc[mt][dnt][0] * inv[mt][0],
                                       oacc[mt][dnt][1] * inv[mt][0]);
            *(float2*)o1 = make_float2(oacc[mt][dnt][2] * inv[mt][1],
                                       oacc[mt][dnt][3] * inv[mt][1]);
        }
    }
}

// ---------------------------------------------------------------------------
extern "C" void kernel_launch(void* const* d_in, const int* in_sizes, int n_in,
                              void* d_out, int out_size) {
    const float* Q    = (const float*)d_in[0];
    const float* K    = (const float*)d_in[1];
    const float* V    = (const float*)d_in[2];
    const float* mask = (const float*)d_in[3];
    const float* Wq   = (const float*)d_in[4];
    const float* Wk   = (const float*)d_in[5];
    const float* Wv   = (const float*)d_in[6];
    const float* Wout = (const float*)d_in[7];
    float* out = (float*)d_out;

    cudaFuncSetAttribute(proj3_mma,   cudaFuncAttributeMaxDynamicSharedMemorySize, GEMM_SMEM);
    cudaFuncSetAttribute(outproj_mma, cudaFuncAttributeMaxDynamicSharedMemorySize, GEMM_SMEM);
    cudaFuncSetAttribute(attn_mma,    cudaFuncAttributeMaxDynamicSharedMemorySize, ATTN_SMEM);

    float* att;
    cudaGetSymbolAddress((void**)&att, g_att);

    wconv<<<64, 256>>>(Wq, Wk, Wv, Wout);
    proj3_mma<<<768, 256, GEMM_SMEM>>>(Q, K, V);
    attn_mma<<<1024, 256, ATTN_SMEM>>>(mask);
    outproj_mma<<<256, 256, GEMM_SMEM>>>(att, out);
}